// round 2
// baseline (speedup 1.0000x reference)
#include <cuda_runtime.h>
#include <math.h>

#define NN 100000
#define EE 3200000
#define F_IN 128
#define H1 32
#define H2 64
#define GG 256
#define ACT 64

#define CHUNK 1024
#define NCHUNK ((NN + CHUNK - 1) / CHUNK)   // 98

// ---------------- scratch (static device globals; no allocation) ----------------
__device__ int   g_deg[NN];
__device__ float g_dinv[NN];
__device__ int   g_off[NN + 1];
__device__ int   g_cur[NN];
__device__ int   g_csr[EE];
__device__ int   g_blocksum[NCHUNK];
__device__ int   g_chunkoff[NCHUNK];
__device__ float g_hn[NN * 64];   // scaled features (hn = h * dinv), layer1 then layer2
__device__ float g_h[NN * 64];    // post-aggregation features
__device__ float g_pool[GG * H2];

// ---------------- degree / CSR build ----------------
__global__ void k_zero_deg() {
    int i = blockIdx.x * blockDim.x + threadIdx.x;
    if (i < NN) g_deg[i] = 0;
}

__global__ void k_deg(const int* __restrict__ dst) {
    int e = blockIdx.x * blockDim.x + threadIdx.x;
    if (e < EE) atomicAdd(&g_deg[dst[e]], 1);
}

// per-chunk sums + dinv
__global__ void k_chunksum() {
    __shared__ int sm[256];
    int b = blockIdx.x, t = threadIdx.x;
    int base = b * CHUNK + t * 4;
    int s = 0;
#pragma unroll
    for (int j = 0; j < 4; j++) {
        int i = base + j;
        if (i < NN) {
            int d = g_deg[i];
            s += d;
            g_dinv[i] = rsqrtf((float)(d + 1));
        }
    }
    sm[t] = s;
    __syncthreads();
    for (int d = 128; d > 0; d >>= 1) {
        if (t < d) sm[t] += sm[t + d];
        __syncthreads();
    }
    if (t == 0) g_blocksum[b] = sm[0];
}

// scan the chunk sums (single block)
__global__ void k_scan_blocks() {
    __shared__ int sm[128];
    int t = threadIdx.x;
    sm[t] = (t < NCHUNK) ? g_blocksum[t] : 0;
    __syncthreads();
    for (int d = 1; d < 128; d <<= 1) {
        int add = (t >= d) ? sm[t - d] : 0;
        __syncthreads();
        sm[t] += add;
        __syncthreads();
    }
    if (t < NCHUNK) g_chunkoff[t] = (t > 0) ? sm[t - 1] : 0;
}

// within-chunk exclusive scan -> g_off, g_cur
__global__ void k_scan_chunks() {
    __shared__ int sm[256];
    int b = blockIdx.x, t = threadIdx.x;
    int base = b * CHUNK + t * 4;
    int v[4];
    int tot = 0;
#pragma unroll
    for (int j = 0; j < 4; j++) {
        int i = base + j;
        v[j] = (i < NN) ? g_deg[i] : 0;
        tot += v[j];
    }
    sm[t] = tot;
    __syncthreads();
    for (int d = 1; d < 256; d <<= 1) {
        int add = (t >= d) ? sm[t - d] : 0;
        __syncthreads();
        sm[t] += add;
        __syncthreads();
    }
    int run = ((t > 0) ? sm[t - 1] : 0) + g_chunkoff[b];
#pragma unroll
    for (int j = 0; j < 4; j++) {
        int i = base + j;
        if (i < NN) {
            g_off[i] = run;
            g_cur[i] = run;
            run += v[j];
            if (i == NN - 1) g_off[NN] = run;
        }
    }
}

__global__ void k_scatter(const int* __restrict__ src, const int* __restrict__ dst) {
    int e = blockIdx.x * blockDim.x + threadIdx.x;
    if (e < EE) {
        int d = dst[e];
        int p = atomicAdd(&g_cur[d], 1);
        g_csr[p] = src[e];
    }
}

// ---------------- layer 1: hn1 = dinv * (x @ W1)   [N,32] ----------------
__global__ __launch_bounds__(256) void k_gemm1(const float* __restrict__ x,
                                               const float* __restrict__ W1) {
    __shared__ float Ws[F_IN * H1];  // 16KB
    for (int i = threadIdx.x; i < F_IN * H1; i += 256) Ws[i] = W1[i];
    __syncthreads();
    int warp = (blockIdx.x * 256 + threadIdx.x) >> 5;
    int lane = threadIdx.x & 31;
    if (warp >= NN) return;
    float4 xv = ((const float4*)x)[warp * 32 + lane];  // x row, 4 vals per lane
    float xr[4] = {xv.x, xv.y, xv.z, xv.w};
    float acc = 0.f;
#pragma unroll
    for (int k = 0; k < F_IN; k++) {
        float xk = __shfl_sync(0xffffffffu, xr[k & 3], k >> 2);
        acc = fmaf(xk, Ws[k * H1 + lane], acc);
    }
    g_hn[warp * H1 + lane] = g_dinv[warp] * acc;
}

// ---------------- agg layer1: h1 = leaky(dinv*(hn[d]+sum hn[src]) + b1) ----------------
__global__ __launch_bounds__(256) void k_agg1(const float* __restrict__ b1) {
    int warp = (blockIdx.x * 256 + threadIdx.x) >> 5;
    int lane = threadIdx.x & 31;
    if (warp >= NN) return;
    float acc = g_hn[warp * H1 + lane];  // self loop
    int beg = g_off[warp], end = g_off[warp + 1];
    int e = beg;
    for (; e + 4 <= end; e += 4) {
        int s0 = g_csr[e], s1 = g_csr[e + 1], s2 = g_csr[e + 2], s3 = g_csr[e + 3];
        float a0 = g_hn[s0 * H1 + lane];
        float a1 = g_hn[s1 * H1 + lane];
        float a2 = g_hn[s2 * H1 + lane];
        float a3 = g_hn[s3 * H1 + lane];
        acc += (a0 + a1) + (a2 + a3);
    }
    for (; e < end; e++) acc += g_hn[g_csr[e] * H1 + lane];
    float r = g_dinv[warp] * acc + b1[lane];
    g_h[warp * H1 + lane] = (r > 0.f) ? r : 0.1f * r;
}

// ---------------- layer 2: hn2 = dinv * (h1 @ W2)   [N,64] ----------------
__global__ __launch_bounds__(256) void k_gemm2(const float* __restrict__ W2) {
    __shared__ float2 Ws[H1 * 32];  // W2 is [32][64] row-major == 1024 float2
    for (int i = threadIdx.x; i < H1 * 32; i += 256)
        Ws[i] = ((const float2*)W2)[i];
    __syncthreads();
    int warp = (blockIdx.x * 256 + threadIdx.x) >> 5;
    int lane = threadIdx.x & 31;
    if (warp >= NN) return;
    float hv = g_h[warp * H1 + lane];
    float a0 = 0.f, a1 = 0.f;
#pragma unroll
    for (int k = 0; k < H1; k++) {
        float hk = __shfl_sync(0xffffffffu, hv, k);
        float2 w = Ws[k * 32 + lane];
        a0 = fmaf(hk, w.x, a0);
        a1 = fmaf(hk, w.y, a1);
    }
    float d = g_dinv[warp];
    float2 o; o.x = d * a0; o.y = d * a1;
    ((float2*)g_hn)[warp * 32 + lane] = o;
}

// ---------------- agg layer2: h2 = dinv*(hn[d]+sum hn[src]) + b2 ----------------
__global__ __launch_bounds__(256) void k_agg2(const float* __restrict__ b2) {
    int warp = (blockIdx.x * 256 + threadIdx.x) >> 5;
    int lane = threadIdx.x & 31;
    if (warp >= NN) return;
    const float2* hn2 = (const float2*)g_hn;
    float2 acc = hn2[warp * 32 + lane];  // self loop
    int beg = g_off[warp], end = g_off[warp + 1];
    int e = beg;
    for (; e + 4 <= end; e += 4) {
        int s0 = g_csr[e], s1 = g_csr[e + 1], s2 = g_csr[e + 2], s3 = g_csr[e + 3];
        float2 a0 = hn2[s0 * 32 + lane];
        float2 a1 = hn2[s1 * 32 + lane];
        float2 a2 = hn2[s2 * 32 + lane];
        float2 a3 = hn2[s3 * 32 + lane];
        acc.x += (a0.x + a1.x) + (a2.x + a3.x);
        acc.y += (a0.y + a1.y) + (a2.y + a3.y);
    }
    for (; e < end; e++) {
        float2 a = hn2[g_csr[e] * 32 + lane];
        acc.x += a.x; acc.y += a.y;
    }
    float d = g_dinv[warp];
    float2 bb = ((const float2*)b2)[lane];
    float2 o; o.x = d * acc.x + bb.x; o.y = d * acc.y + bb.y;
    ((float2*)g_h)[warp * 32 + lane] = o;
}

// ---------------- max pool over batch ----------------
__global__ void k_pool_init() {
    int i = blockIdx.x * blockDim.x + threadIdx.x;
    if (i < GG * H2) g_pool[i] = -INFINITY;
}

__device__ __forceinline__ void atomicMaxFloat(float* addr, float val) {
    if (val >= 0.f)
        atomicMax((int*)addr, __float_as_int(val));
    else
        atomicMin((unsigned int*)addr, __float_as_uint(val));
}

__global__ void k_pool(const int* __restrict__ batch) {
    long long idx = (long long)blockIdx.x * blockDim.x + threadIdx.x;
    if (idx < (long long)NN * H2) {
        int node = (int)(idx >> 6);
        int c = (int)(idx & 63);
        float v = g_h[idx];
        atomicMaxFloat(&g_pool[batch[node] * H2 + c], v);
    }
}

// ---------------- MLP head: one block per graph ----------------
__global__ __launch_bounds__(128) void k_mlp(const float* __restrict__ l1W, const float* __restrict__ l1b,
                                             const float* __restrict__ l2W, const float* __restrict__ l2b,
                                             const float* __restrict__ l3W, const float* __restrict__ l3b,
                                             float* __restrict__ out) {
    __shared__ float gv[H2];
    __shared__ float z1[128];
    __shared__ float z2[64];
    int g = blockIdx.x, t = threadIdx.x;
    if (t < H2) gv[t] = g_pool[g * H2 + t];
    __syncthreads();
    // z1 = leaky(gv @ l1W + l1b)  -> [128]
    {
        float s = 0.f;
#pragma unroll
        for (int k = 0; k < H2; k++) s = fmaf(gv[k], l1W[k * 128 + t], s);
        s += l1b[t];
        z1[t] = (s > 0.f) ? s : 0.1f * s;
    }
    __syncthreads();
    // z2 = leaky(z1 @ l2W + l2b)  -> [64]
    if (t < 64) {
        float s = 0.f;
#pragma unroll
        for (int k = 0; k < 128; k++) s = fmaf(z1[k], l2W[k * 64 + t], s);
        s += l2b[t];
        z2[t] = (s > 0.f) ? s : 0.1f * s;
    }
    __syncthreads();
    // out = z2 @ l3W + l3b  -> [64]
    if (t < ACT) {
        float s = 0.f;
#pragma unroll
        for (int k = 0; k < 64; k++) s = fmaf(z2[k], l3W[k * ACT + t], s);
        out[g * ACT + t] = s + l3b[t];
    }
}

// ---------------- launch ----------------
extern "C" void kernel_launch(void* const* d_in, const int* in_sizes, int n_in,
                              void* d_out, int out_size) {
    const float* x    = (const float*)d_in[0];
    const int*   ei   = (const int*)d_in[1];   // [2,E]
    const int*   bat  = (const int*)d_in[2];
    const float* W1   = (const float*)d_in[3];
    const float* b1   = (const float*)d_in[4];
    const float* W2   = (const float*)d_in[5];
    const float* b2   = (const float*)d_in[6];
    const float* l1W  = (const float*)d_in[7];
    const float* l1b  = (const float*)d_in[8];
    const float* l2W  = (const float*)d_in[9];
    const float* l2b  = (const float*)d_in[10];
    const float* l3W  = (const float*)d_in[11];
    const float* l3b  = (const float*)d_in[12];
    float* out = (float*)d_out;
    const int* src = ei;
    const int* dst = ei + EE;

    const int NB_N = (NN + 255) / 256;           // 391
    const int NB_E = (EE + 255) / 256;           // 12500
    const int NB_W = (NN + 7) / 8;               // 12500 (warp per node, 8 warps/block)
    const int NB_P = (NN * H2 + 255) / 256;      // 25000

    k_zero_deg<<<NB_N, 256>>>();
    k_deg<<<NB_E, 256>>>(dst);
    k_chunksum<<<NCHUNK, 256>>>();
    k_scan_blocks<<<1, 128>>>();
    k_scan_chunks<<<NCHUNK, 256>>>();
    k_scatter<<<NB_E, 256>>>(src, dst);

    k_gemm1<<<NB_W, 256>>>(x, W1);
    k_agg1<<<NB_W, 256>>>(b1);
    k_gemm2<<<NB_W, 256>>>(W2);
    k_agg2<<<NB_W, 256>>>(b2);

    k_pool_init<<<(GG * H2 + 255) / 256, 256>>>();
    k_pool<<<NB_P, 256>>>(bat);
    k_mlp<<<GG, 128>>>(l1W, l1b, l2W, l2b, l3W, l3b, out);
}

// round 4
// speedup vs baseline: 1.0884x; 1.0884x over previous
#include <cuda_runtime.h>
#include <cuda_fp16.h>
#include <math.h>

#define NN 100000
#define EE 3200000
#define F_IN 128
#define H1 32
#define H2 64
#define GG 256
#define ACT 64

#define CHUNK 1024
#define NCHUNK ((NN + CHUNK - 1) / CHUNK)   // 98

// ---------------- scratch (static device globals; no allocation) ----------------
__device__ int    g_deg[NN];
__device__ float  g_dinv[NN];
__device__ int    g_off[NN + 1];
__device__ int    g_cur[NN];
__device__ int    g_csr[EE];
__device__ int    g_blocksum[NCHUNK];
__device__ int    g_chunkoff[NCHUNK];
__device__ __half g_hn1[NN * H1];   // scaled layer-1 features (fp16 storage)
__device__ __half g_hn2[NN * H2];   // scaled layer-2 features (fp16 storage)
__device__ float  g_pool[GG * H2];

// ---------------- init: zero degrees + pool to -inf ----------------
__global__ void k_init() {
    int i = blockIdx.x * blockDim.x + threadIdx.x;
    if (i < NN) g_deg[i] = 0;
    if (i < GG * H2) g_pool[i] = -INFINITY;
}

__global__ void k_deg(const int* __restrict__ dst) {
    int e = blockIdx.x * blockDim.x + threadIdx.x;
    if (e < EE) atomicAdd(&g_deg[dst[e]], 1);
}

// per-chunk sums + dinv
__global__ void k_chunksum() {
    __shared__ int sm[256];
    int b = blockIdx.x, t = threadIdx.x;
    int base = b * CHUNK + t * 4;
    int s = 0;
#pragma unroll
    for (int j = 0; j < 4; j++) {
        int i = base + j;
        if (i < NN) {
            int d = g_deg[i];
            s += d;
            g_dinv[i] = rsqrtf((float)(d + 1));
        }
    }
    sm[t] = s;
    __syncthreads();
    for (int d = 128; d > 0; d >>= 1) {
        if (t < d) sm[t] += sm[t + d];
        __syncthreads();
    }
    if (t == 0) g_blocksum[b] = sm[0];
}

__global__ void k_scan_blocks() {
    __shared__ int sm[128];
    int t = threadIdx.x;
    sm[t] = (t < NCHUNK) ? g_blocksum[t] : 0;
    __syncthreads();
    for (int d = 1; d < 128; d <<= 1) {
        int add = (t >= d) ? sm[t - d] : 0;
        __syncthreads();
        sm[t] += add;
        __syncthreads();
    }
    if (t < NCHUNK) g_chunkoff[t] = (t > 0) ? sm[t - 1] : 0;
}

__global__ void k_scan_chunks() {
    __shared__ int sm[256];
    int b = blockIdx.x, t = threadIdx.x;
    int base = b * CHUNK + t * 4;
    int v[4];
    int tot = 0;
#pragma unroll
    for (int j = 0; j < 4; j++) {
        int i = base + j;
        v[j] = (i < NN) ? g_deg[i] : 0;
        tot += v[j];
    }
    sm[t] = tot;
    __syncthreads();
    for (int d = 1; d < 256; d <<= 1) {
        int add = (t >= d) ? sm[t - d] : 0;
        __syncthreads();
        sm[t] += add;
        __syncthreads();
    }
    int run = ((t > 0) ? sm[t - 1] : 0) + g_chunkoff[b];
#pragma unroll
    for (int j = 0; j < 4; j++) {
        int i = base + j;
        if (i < NN) {
            g_off[i] = run;
            g_cur[i] = run;
            run += v[j];
            if (i == NN - 1) g_off[NN] = run;
        }
    }
}

__global__ void k_scatter(const int* __restrict__ src, const int* __restrict__ dst) {
    int e = blockIdx.x * blockDim.x + threadIdx.x;
    if (e < EE) {
        int d = dst[e];
        int p = atomicAdd(&g_cur[d], 1);
        g_csr[p] = src[e];
    }
}

// ---------------- layer 1 GEMM (tiled): hn1 = fp16(dinv * (x @ W1)) ----------------
#define TILE_N 64
__global__ __launch_bounds__(256) void k_gemm1(const float* __restrict__ x,
                                               const float* __restrict__ W1) {
    __shared__ float xs[TILE_N][132];        // padded: stride 132 -> conflict-free
    __shared__ float Ws[F_IN][H1];           // 16KB, [k][c]
    int base = blockIdx.x * TILE_N;
    for (int i = threadIdx.x; i < (F_IN * H1) / 4; i += 256)
        ((float4*)Ws)[i] = ((const float4*)W1)[i];
    for (int i = threadIdx.x; i < TILE_N * 32; i += 256) {
        int r = i >> 5, c4 = i & 31;
        int row = base + r;
        float4 v = (row < NN) ? ((const float4*)x)[row * 32 + c4]
                              : make_float4(0.f, 0.f, 0.f, 0.f);
        *(float4*)&xs[r][c4 * 4] = v;
    }
    __syncthreads();
    int t = threadIdx.x;
    int cg = (t & 7) * 4;        // 4 channels
    int n0 = (t >> 3) * 2;       // 2 local nodes
    float a0[4] = {0.f, 0.f, 0.f, 0.f};
    float a1[4] = {0.f, 0.f, 0.f, 0.f};
#pragma unroll 8
    for (int k = 0; k < F_IN; k++) {
        float4 w = *(const float4*)&Ws[k][cg];
        float x0 = xs[n0][k];
        float x1 = xs[n0 + 1][k];
        a0[0] = fmaf(x0, w.x, a0[0]); a0[1] = fmaf(x0, w.y, a0[1]);
        a0[2] = fmaf(x0, w.z, a0[2]); a0[3] = fmaf(x0, w.w, a0[3]);
        a1[0] = fmaf(x1, w.x, a1[0]); a1[1] = fmaf(x1, w.y, a1[1]);
        a1[2] = fmaf(x1, w.z, a1[2]); a1[3] = fmaf(x1, w.w, a1[3]);
    }
    __half2* hn1 = (__half2*)g_hn1;
    int r0 = base + n0;
    if (r0 < NN) {
        float d = g_dinv[r0];
        hn1[r0 * 16 + (cg >> 1)]     = __floats2half2_rn(d * a0[0], d * a0[1]);
        hn1[r0 * 16 + (cg >> 1) + 1] = __floats2half2_rn(d * a0[2], d * a0[3]);
    }
    int r1 = r0 + 1;
    if (r1 < NN) {
        float d = g_dinv[r1];
        hn1[r1 * 16 + (cg >> 1)]     = __floats2half2_rn(d * a1[0], d * a1[1]);
        hn1[r1 * 16 + (cg >> 1) + 1] = __floats2half2_rn(d * a1[2], d * a1[3]);
    }
}

// ---------------- fused agg1 + leaky + gemm2 + scale: hn2 = fp16(dinv*(h1@W2)) ----------------
__global__ __launch_bounds__(256) void k_agg1(const float* __restrict__ b1,
                                              const float* __restrict__ W2) {
    __shared__ float2 W2s[H1 * 32];  // W2 [32][64] row-major == [32][32] float2
    for (int i = threadIdx.x; i < H1 * 32; i += 256)
        W2s[i] = ((const float2*)W2)[i];
    __syncthreads();
    int warp = (blockIdx.x * 256 + threadIdx.x) >> 5;
    int lane = threadIdx.x & 31;
    if (warp >= NN) return;
    const __half* hn1 = g_hn1;
    float acc = __half2float(hn1[warp * H1 + lane]);  // self loop
    int beg = g_off[warp], end = g_off[warp + 1];
    int e = beg;
    for (; e + 4 <= end; e += 4) {
        int s0 = g_csr[e], s1 = g_csr[e + 1], s2 = g_csr[e + 2], s3 = g_csr[e + 3];
        float f0 = __half2float(hn1[s0 * H1 + lane]);
        float f1 = __half2float(hn1[s1 * H1 + lane]);
        float f2 = __half2float(hn1[s2 * H1 + lane]);
        float f3 = __half2float(hn1[s3 * H1 + lane]);
        acc += (f0 + f1) + (f2 + f3);
    }
    for (; e < end; e++) acc += __half2float(hn1[g_csr[e] * H1 + lane]);
    float r = g_dinv[warp] * acc + b1[lane];
    r = (r > 0.f) ? r : 0.1f * r;   // h1 value for this (node, lane)
    // fused gemm2: this lane owns output channels (2*lane, 2*lane+1)
    float z0 = 0.f, z1 = 0.f;
#pragma unroll
    for (int k = 0; k < H1; k++) {
        float hk = __shfl_sync(0xffffffffu, r, k);
        float2 w = W2s[k * 32 + lane];
        z0 = fmaf(hk, w.x, z0);
        z1 = fmaf(hk, w.y, z1);
    }
    float d = g_dinv[warp];
    ((__half2*)g_hn2)[warp * 32 + lane] = __floats2half2_rn(d * z0, d * z1);
}

// ---------------- sign-split float atomic max (no-return -> RED) ----------------
__device__ __forceinline__ void atomicMaxFloat(float* addr, float val) {
    if (val >= 0.f)
        atomicMax((int*)addr, __float_as_int(val));
    else
        atomicMin((unsigned int*)addr, __float_as_uint(val));
}

// ---------------- fused agg2 + bias + global max pool ----------------
__global__ __launch_bounds__(256) void k_agg2(const float* __restrict__ b2,
                                              const int* __restrict__ batch) {
    int warp = (blockIdx.x * 256 + threadIdx.x) >> 5;
    int lane = threadIdx.x & 31;
    if (warp >= NN) return;
    const __half2* hn2 = (const __half2*)g_hn2;
    float2 s = __half22float2(hn2[warp * 32 + lane]);  // self loop
    float ax = s.x, ay = s.y;
    int beg = g_off[warp], end = g_off[warp + 1];
    int e = beg;
    for (; e + 4 <= end; e += 4) {
        int s0 = g_csr[e], s1 = g_csr[e + 1], s2 = g_csr[e + 2], s3 = g_csr[e + 3];
        float2 f0 = __half22float2(hn2[s0 * 32 + lane]);
        float2 f1 = __half22float2(hn2[s1 * 32 + lane]);
        float2 f2 = __half22float2(hn2[s2 * 32 + lane]);
        float2 f3 = __half22float2(hn2[s3 * 32 + lane]);
        ax += (f0.x + f1.x) + (f2.x + f3.x);
        ay += (f0.y + f1.y) + (f2.y + f3.y);
    }
    for (; e < end; e++) {
        float2 f = __half22float2(hn2[g_csr[e] * 32 + lane]);
        ax += f.x; ay += f.y;
    }
    float d = g_dinv[warp];
    float2 bb = ((const float2*)b2)[lane];
    float ox = d * ax + bb.x;
    float oy = d * ay + bb.y;
    int gidx = batch[warp];
    atomicMaxFloat(&g_pool[gidx * H2 + 2 * lane], ox);
    atomicMaxFloat(&g_pool[gidx * H2 + 2 * lane + 1], oy);
}

// ---------------- MLP head: one block per graph ----------------
__global__ __launch_bounds__(128) void k_mlp(const float* __restrict__ l1W, const float* __restrict__ l1b,
                                             const float* __restrict__ l2W, const float* __restrict__ l2b,
                                             const float* __restrict__ l3W, const float* __restrict__ l3b,
                                             float* __restrict__ out) {
    __shared__ float gv[H2];
    __shared__ float z1[128];
    __shared__ float z2[64];
    int g = blockIdx.x, t = threadIdx.x;
    if (t < H2) gv[t] = g_pool[g * H2 + t];
    __syncthreads();
    {
        float s = 0.f;
#pragma unroll
        for (int k = 0; k < H2; k++) s = fmaf(gv[k], l1W[k * 128 + t], s);
        s += l1b[t];
        z1[t] = (s > 0.f) ? s : 0.1f * s;
    }
    __syncthreads();
    if (t < 64) {
        float s = 0.f;
#pragma unroll
        for (int k = 0; k < 128; k++) s = fmaf(z1[k], l2W[k * 64 + t], s);
        s += l2b[t];
        z2[t] = (s > 0.f) ? s : 0.1f * s;
    }
    __syncthreads();
    if (t < ACT) {
        float s = 0.f;
#pragma unroll
        for (int k = 0; k < 64; k++) s = fmaf(z2[k], l3W[k * ACT + t], s);
        out[g * ACT + t] = s + l3b[t];
    }
}

// ---------------- launch ----------------
extern "C" void kernel_launch(void* const* d_in, const int* in_sizes, int n_in,
                              void* d_out, int out_size) {
    const float* x    = (const float*)d_in[0];
    const int*   ei   = (const int*)d_in[1];   // [2,E]
    const int*   bat  = (const int*)d_in[2];
    const float* W1   = (const float*)d_in[3];
    const float* b1   = (const float*)d_in[4];
    const float* W2   = (const float*)d_in[5];
    const float* b2   = (const float*)d_in[6];
    const float* l1W  = (const float*)d_in[7];
    const float* l1b  = (const float*)d_in[8];
    const float* l2W  = (const float*)d_in[9];
    const float* l2b  = (const float*)d_in[10];
    const float* l3W  = (const float*)d_in[11];
    const float* l3b  = (const float*)d_in[12];
    float* out = (float*)d_out;
    const int* src = ei;
    const int* dst = ei + EE;

    const int NB_N = (NN + 255) / 256;           // 391
    const int NB_E = (EE + 255) / 256;           // 12500
    const int NB_W = (NN + 7) / 8;               // 12500 (warp per node)
    const int NB_G1 = (NN + TILE_N - 1) / TILE_N; // 1563

    k_init<<<NB_N, 256>>>();
    k_deg<<<NB_E, 256>>>(dst);
    k_chunksum<<<NCHUNK, 256>>>();
    k_scan_blocks<<<1, 128>>>();
    k_scan_chunks<<<NCHUNK, 256>>>();
    k_scatter<<<NB_E, 256>>>(src, dst);

    k_gemm1<<<NB_G1, 256>>>(x, W1);
    k_agg1<<<NB_W, 256>>>(b1, W2);
    k_agg2<<<NB_W, 256>>>(b2, bat);

    k_mlp<<<GG, 128>>>(l1W, l1b, l2W, l2b, l3W, l3b, out);
}

// round 7
// speedup vs baseline: 1.2135x; 1.1150x over previous
#include <cuda_runtime.h>
#include <cuda_fp16.h>
#include <math.h>

#define NN 100000
#define EE 3200000
#define F_IN 128
#define H1 32
#define H2 64
#define GG 256
#define ACT 64

#define CHUNK 1024
#define NCHUNK ((NN + CHUNK - 1) / CHUNK)   // 98

// ---------------- scratch (static device globals; no allocation) ----------------
__device__ int    g_deg[NN];
__device__ float  g_dinv[NN];
__device__ int    g_off[NN + 1];
__device__ int    g_cur[NN];
__device__ int    g_csr[EE];
__device__ int    g_blocksum[NCHUNK];
__device__ int    g_chunkoff[NCHUNK];
__device__ __half g_hn1[NN * H1];   // hn1 = dinv * (x @ W1)         [N,32] fp16
__device__ __half g_p[NN * H1];     // p   = dinv * h1               [N,32] fp16
__device__ float  g_pool[GG * H2];

// ---------------- init: zero degrees + pool to -inf ----------------
__global__ void k_init() {
    int i = blockIdx.x * blockDim.x + threadIdx.x;
    if (i < NN) g_deg[i] = 0;
    if (i < GG * H2) g_pool[i] = -INFINITY;
}

__global__ void k_deg(const int* __restrict__ dst) {
    int e = blockIdx.x * blockDim.x + threadIdx.x;
    if (e < EE) atomicAdd(&g_deg[dst[e]], 1);
}

// per-chunk sums + dinv
__global__ void k_chunksum() {
    __shared__ int sm[256];
    int b = blockIdx.x, t = threadIdx.x;
    int base = b * CHUNK + t * 4;
    int s = 0;
#pragma unroll
    for (int j = 0; j < 4; j++) {
        int i = base + j;
        if (i < NN) {
            int d = g_deg[i];
            s += d;
            g_dinv[i] = rsqrtf((float)(d + 1));
        }
    }
    sm[t] = s;
    __syncthreads();
    for (int d = 128; d > 0; d >>= 1) {
        if (t < d) sm[t] += sm[t + d];
        __syncthreads();
    }
    if (t == 0) g_blocksum[b] = sm[0];
}

__global__ void k_scan_blocks() {
    __shared__ int sm[128];
    int t = threadIdx.x;
    sm[t] = (t < NCHUNK) ? g_blocksum[t] : 0;
    __syncthreads();
    for (int d = 1; d < 128; d <<= 1) {
        int add = (t >= d) ? sm[t - d] : 0;
        __syncthreads();
        sm[t] += add;
        __syncthreads();
    }
    if (t < NCHUNK) g_chunkoff[t] = (t > 0) ? sm[t - 1] : 0;
}

__global__ void k_scan_chunks() {
    __shared__ int sm[256];
    int b = blockIdx.x, t = threadIdx.x;
    int base = b * CHUNK + t * 4;
    int v[4];
    int tot = 0;
#pragma unroll
    for (int j = 0; j < 4; j++) {
        int i = base + j;
        v[j] = (i < NN) ? g_deg[i] : 0;
        tot += v[j];
    }
    sm[t] = tot;
    __syncthreads();
    for (int d = 1; d < 256; d <<= 1) {
        int add = (t >= d) ? sm[t - d] : 0;
        __syncthreads();
        sm[t] += add;
        __syncthreads();
    }
    int run = ((t > 0) ? sm[t - 1] : 0) + g_chunkoff[b];
#pragma unroll
    for (int j = 0; j < 4; j++) {
        int i = base + j;
        if (i < NN) {
            g_off[i] = run;
            g_cur[i] = run;
            run += v[j];
            if (i == NN - 1) g_off[NN] = run;
        }
    }
}

__global__ void k_scatter(const int* __restrict__ src, const int* __restrict__ dst) {
    int e = blockIdx.x * blockDim.x + threadIdx.x;
    if (e < EE) {
        int d = dst[e];
        int p = atomicAdd(&g_cur[d], 1);
        g_csr[p] = src[e];
    }
}

// ---------------- layer 1 GEMM (tiled): hn1 = fp16(dinv * (x @ W1)) ----------------
#define TILE_N 64
__global__ __launch_bounds__(256) void k_gemm1(const float* __restrict__ x,
                                               const float* __restrict__ W1) {
    __shared__ float xs[TILE_N][132];        // padded: stride 132 -> conflict-free
    __shared__ float Ws[F_IN][H1];           // 16KB, [k][c]
    int base = blockIdx.x * TILE_N;
    for (int i = threadIdx.x; i < (F_IN * H1) / 4; i += 256)
        ((float4*)Ws)[i] = ((const float4*)W1)[i];
    for (int i = threadIdx.x; i < TILE_N * 32; i += 256) {
        int r = i >> 5, c4 = i & 31;
        int row = base + r;
        float4 v = (row < NN) ? ((const float4*)x)[row * 32 + c4]
                              : make_float4(0.f, 0.f, 0.f, 0.f);
        *(float4*)&xs[r][c4 * 4] = v;
    }
    __syncthreads();
    int t = threadIdx.x;
    int cg = (t & 7) * 4;        // 4 channels
    int n0 = (t >> 3) * 2;       // 2 local nodes
    float a0[4] = {0.f, 0.f, 0.f, 0.f};
    float a1[4] = {0.f, 0.f, 0.f, 0.f};
#pragma unroll 8
    for (int k = 0; k < F_IN; k++) {
        float4 w = *(const float4*)&Ws[k][cg];
        float x0 = xs[n0][k];
        float x1 = xs[n0 + 1][k];
        a0[0] = fmaf(x0, w.x, a0[0]); a0[1] = fmaf(x0, w.y, a0[1]);
        a0[2] = fmaf(x0, w.z, a0[2]); a0[3] = fmaf(x0, w.w, a0[3]);
        a1[0] = fmaf(x1, w.x, a1[0]); a1[1] = fmaf(x1, w.y, a1[1]);
        a1[2] = fmaf(x1, w.z, a1[2]); a1[3] = fmaf(x1, w.w, a1[3]);
    }
    __half2* hn1 = (__half2*)g_hn1;
    int r0 = base + n0;
    if (r0 < NN) {
        float d = g_dinv[r0];
        hn1[r0 * 16 + (cg >> 1)]     = __floats2half2_rn(d * a0[0], d * a0[1]);
        hn1[r0 * 16 + (cg >> 1) + 1] = __floats2half2_rn(d * a0[2], d * a0[3]);
    }
    int r1 = r0 + 1;
    if (r1 < NN) {
        float d = g_dinv[r1];
        hn1[r1 * 16 + (cg >> 1)]     = __floats2half2_rn(d * a1[0], d * a1[1]);
        hn1[r1 * 16 + (cg >> 1) + 1] = __floats2half2_rn(d * a1[2], d * a1[3]);
    }
}

// ---------------- shared gather core ----------------
// Warp per node. lane = (side<<4) | pair; pair = channel pair (2p,2p+1),
// side = edge parity. Each lane loads __half2 (4B); 16 lanes cover a 64B row;
// the warp streams 2 edges concurrently. After the loop, shfl_xor(16) merges
// the two parity accumulators; then ALL lanes hold the full pair-sum.
__device__ __forceinline__ float2 gather_sum(const __half2* __restrict__ H,
                                             int node, int pair, int side) {
    float2 acc = make_float2(0.f, 0.f);
    if (side == 0) {  // self loop
        float2 s = __half22float2(H[node * 16 + pair]);
        acc.x = s.x; acc.y = s.y;
    }
    int beg = g_off[node], end = g_off[node + 1];
    int e = beg + side;
    // unroll: 4 edges per side per iteration (8 edges per warp)
    while (e + 6 < end) {
        int s0 = g_csr[e], s1 = g_csr[e + 2], s2 = g_csr[e + 4], s3 = g_csr[e + 6];
        float2 f0 = __half22float2(H[s0 * 16 + pair]);
        float2 f1 = __half22float2(H[s1 * 16 + pair]);
        float2 f2 = __half22float2(H[s2 * 16 + pair]);
        float2 f3 = __half22float2(H[s3 * 16 + pair]);
        acc.x += (f0.x + f1.x) + (f2.x + f3.x);
        acc.y += (f0.y + f1.y) + (f2.y + f3.y);
        e += 8;
    }
    while (e < end) {
        float2 f = __half22float2(H[g_csr[e] * 16 + pair]);
        acc.x += f.x; acc.y += f.y;
        e += 2;
    }
    acc.x += __shfl_xor_sync(0xffffffffu, acc.x, 16);
    acc.y += __shfl_xor_sync(0xffffffffu, acc.y, 16);
    return acc;
}

// ---------------- agg1: p = fp16( dinv * leaky(dinv*sum + b1) ) ----------------
__global__ __launch_bounds__(256) void k_agg1(const float* __restrict__ b1) {
    int warp = (blockIdx.x * 256 + threadIdx.x) >> 5;
    int lane = threadIdx.x & 31;
    if (warp >= NN) return;
    int pair = lane & 15, side = lane >> 4;
    float2 acc = gather_sum((const __half2*)g_hn1, warp, pair, side);
    float d = g_dinv[warp];
    float2 bb = ((const float2*)b1)[pair];
    float rx = d * acc.x + bb.x;
    float ry = d * acc.y + bb.y;
    rx = (rx > 0.f) ? rx : 0.1f * rx;
    ry = (ry > 0.f) ? ry : 0.1f * ry;
    if (side == 0)
        ((__half2*)g_p)[warp * 16 + pair] = __floats2half2_rn(d * rx, d * ry);
}

// ---------------- sign-split float atomic max (no-return -> RED) ----------------
__device__ __forceinline__ void atomicMaxFloat(float* addr, float val) {
    if (val >= 0.f)
        atomicMax((int*)addr, __float_as_int(val));
    else
        atomicMin((unsigned int*)addr, __float_as_uint(val));
}

// ---------------- agg2: h2 = dinv*(q@W2) + b2 ; fused max pool ----------------
__global__ __launch_bounds__(256) void k_agg2(const float* __restrict__ W2,
                                              const float* __restrict__ b2,
                                              const int* __restrict__ batch) {
    __shared__ float2 W2s[H1 * 32];  // W2 [32][64] row-major == [32][32] float2
    for (int i = threadIdx.x; i < H1 * 32; i += 256)
        W2s[i] = ((const float2*)W2)[i];
    __syncthreads();
    int warp = (blockIdx.x * 256 + threadIdx.x) >> 5;
    int lane = threadIdx.x & 31;
    if (warp >= NN) return;
    int pair = lane & 15, side = lane >> 4;
    float2 acc = gather_sum((const __half2*)g_p, warp, pair, side);
    // q[2j] = acc.x at lane j (mod 16); q[2j+1] = acc.y at lane j
    // output channels for this lane: 2*lane, 2*lane+1
    float z0 = 0.f, z1 = 0.f;
#pragma unroll
    for (int k = 0; k < H1; k++) {
        float qk = __shfl_sync(0xffffffffu, (k & 1) ? acc.y : acc.x, (k >> 1) & 15);
        float2 w = W2s[k * 32 + lane];
        z0 = fmaf(qk, w.x, z0);
        z1 = fmaf(qk, w.y, z1);
    }
    float d = g_dinv[warp];
    float2 bb = ((const float2*)b2)[lane];
    float ox = d * z0 + bb.x;
    float oy = d * z1 + bb.y;
    int gidx = batch[warp];
    atomicMaxFloat(&g_pool[gidx * H2 + 2 * lane], ox);
    atomicMaxFloat(&g_pool[gidx * H2 + 2 * lane + 1], oy);
}

// ---------------- MLP head: one block per graph ----------------
__global__ __launch_bounds__(128) void k_mlp(const float* __restrict__ l1W, const float* __restrict__ l1b,
                                             const float* __restrict__ l2W, const float* __restrict__ l2b,
                                             const float* __restrict__ l3W, const float* __restrict__ l3b,
                                             float* __restrict__ out) {
    __shared__ float gv[H2];
    __shared__ float z1[128];
    __shared__ float z2[64];
    int g = blockIdx.x, t = threadIdx.x;
    if (t < H2) gv[t] = g_pool[g * H2 + t];
    __syncthreads();
    {
        float s = 0.f;
#pragma unroll
        for (int k = 0; k < H2; k++) s = fmaf(gv[k], l1W[k * 128 + t], s);
        s += l1b[t];
        z1[t] = (s > 0.f) ? s : 0.1f * s;
    }
    __syncthreads();
    if (t < 64) {
        float s = 0.f;
#pragma unroll
        for (int k = 0; k < 128; k++) s = fmaf(z1[k], l2W[k * 64 + t], s);
        s += l2b[t];
        z2[t] = (s > 0.f) ? s : 0.1f * s;
    }
    __syncthreads();
    if (t < ACT) {
        float s = 0.f;
#pragma unroll
        for (int k = 0; k < 64; k++) s = fmaf(z2[k], l3W[k * ACT + t], s);
        out[g * ACT + t] = s + l3b[t];
    }
}

// ---------------- launch ----------------
extern "C" void kernel_launch(void* const* d_in, const int* in_sizes, int n_in,
                              void* d_out, int out_size) {
    const float* x    = (const float*)d_in[0];
    const int*   ei   = (const int*)d_in[1];   // [2,E]
    const int*   bat  = (const int*)d_in[2];
    const float* W1   = (const float*)d_in[3];
    const float* b1   = (const float*)d_in[4];
    const float* W2   = (const float*)d_in[5];
    const float* b2   = (const float*)d_in[6];
    const float* l1W  = (const float*)d_in[7];
    const float* l1b  = (const float*)d_in[8];
    const float* l2W  = (const float*)d_in[9];
    const float* l2b  = (const float*)d_in[10];
    const float* l3W  = (const float*)d_in[11];
    const float* l3b  = (const float*)d_in[12];
    float* out = (float*)d_out;
    const int* src = ei;
    const int* dst = ei + EE;

    const int NB_N = (NN + 255) / 256;            // 391
    const int NB_E = (EE + 255) / 256;            // 12500
    const int NB_W = (NN + 7) / 8;                // 12500 (warp per node)
    const int NB_G1 = (NN + TILE_N - 1) / TILE_N; // 1563

    k_init<<<NB_N, 256>>>();
    k_deg<<<NB_E, 256>>>(dst);
    k_chunksum<<<NCHUNK, 256>>>();
    k_scan_blocks<<<1, 128>>>();
    k_scan_chunks<<<NCHUNK, 256>>>();
    k_scatter<<<NB_E, 256>>>(src, dst);

    k_gemm1<<<NB_G1, 256>>>(x, W1);
    k_agg1<<<NB_W, 256>>>(b1);
    k_agg2<<<NB_W, 256>>>(W2, b2, bat);

    k_mlp<<<GG, 128>>>(l1W, l1b, l2W, l2b, l3W, l3b, out);
}